// round 3
// baseline (speedup 1.0000x reference)
#include <cuda_runtime.h>

// ---------------------------------------------------------------------------
// edge_exists_predictor: GCNConv(64->60) -> GCNConv(60->50) -> global_add_pool
//                        -> 4 linear layers (no nonlinearities anywhere).
//
// Entire network is LINEAR => fold all weight matrices into a single
// 64-vector w1c and three scalars (c1, c2, cb). Per-node state collapses to a
// single float propagated through two scalar GCN aggregations.
//
//   w2c = W2 @ (Wf1 @ Wf2 @ Wf3 @ Wo)      [60]
//   w1c = W1 @ w2c                          [64]
//   c1  = b1 . w2c      c2 = b2 . Wcomb     cb = folded MLP bias
//
//   t0[i] = x[i] . w1c
//   t1    = Agg(t0) + c1          Agg(t)[i] = dinv_i*(sum_{e:dst=i} dinv_src*t_src
//   s     = Agg(t1) + c2                        + dinv_i * t_i)
//   out[g]= sum_{i in g} s[i] + cb
// ---------------------------------------------------------------------------

#define NMAX 100000
#define FIN  64

__device__ int   g_is64;          // 1 if edge_index/batch are int64, 0 if int32
__device__ int   g_deg[NMAX];     // in-degree (edges only)
__device__ float g_dinv[NMAX];    // rsqrt(deg+1)
__device__ float g_t[NMAX];       // current node scalar
__device__ float g_p[NMAX];       // dinv * t (prescaled for gathering)
__device__ float g_acc1[NMAX];    // layer-1 scatter accumulator
__device__ float g_acc2[NMAX];    // layer-2 scatter accumulator
__device__ float g_w1c[FIN];      // folded input weight vector
__device__ float g_cst[3];        // c1, c2, cb

__device__ __forceinline__ int load_idx(const void* p, int i) {
    return g_is64 ? (int)((const long long*)p)[i] : ((const int*)p)[i];
}

// --- dtype detection: int64 little-endian => all odd int32 words are 0 ------
__global__ void k_detect(const int* ei32) {
    if (threadIdx.x == 0) {
        int z = ei32[1] | ei32[3] | ei32[5] | ei32[7] | ei32[9] | ei32[11];
        g_is64 = (z == 0) ? 1 : 0;
    }
}

__global__ void k_zero(int n) {
    int i = blockIdx.x * blockDim.x + threadIdx.x;
    if (i < n) { g_deg[i] = 0; g_acc1[i] = 0.f; g_acc2[i] = 0.f; }
}

__global__ void k_deg(const void* ei, int E) {
    int e = blockIdx.x * blockDim.x + threadIdx.x;
    if (e >= E) return;
    int d = load_idx(ei, E + e);
    atomicAdd(&g_deg[d], 1);
}

__global__ void k_dinv(int n) {
    int i = blockIdx.x * blockDim.x + threadIdx.x;
    if (i < n) g_dinv[i] = rsqrtf((float)(g_deg[i] + 1));
}

// --- fold all weights into w1c + 3 scalars (single tiny block) --------------
__global__ void k_fold(const float* W1, const float* b1,
                       const float* W2, const float* b2,
                       const float* Wf1, const float* bf1,
                       const float* Wf2, const float* bf2,
                       const float* Wf3, const float* bf3,
                       const float* Wo,  const float* bo) {
    __shared__ float v3[20], v2[30], v1[50], w2c[60];
    int t = threadIdx.x;
    if (t < 20) { float s = 0.f; for (int j = 0; j < 10; j++) s += Wf3[t*10+j] * Wo[j]; v3[t] = s; }
    __syncthreads();
    if (t < 30) { float s = 0.f; for (int j = 0; j < 20; j++) s += Wf2[t*20+j] * v3[j]; v2[t] = s; }
    __syncthreads();
    if (t < 50) { float s = 0.f; for (int j = 0; j < 30; j++) s += Wf1[t*30+j] * v2[j]; v1[t] = s; }
    __syncthreads();
    if (t < 60) { float s = 0.f; for (int j = 0; j < 50; j++) s += W2[t*50+j] * v1[j]; w2c[t] = s; }
    __syncthreads();
    if (t < 64) { float s = 0.f; for (int j = 0; j < 60; j++) s += W1[t*60+j] * w2c[j]; g_w1c[t] = s; }
    if (t == 0) {
        float c1 = 0.f; for (int j = 0; j < 60; j++) c1 += b1[j] * w2c[j];
        float c2 = 0.f; for (int j = 0; j < 50; j++) c2 += b2[j] * v1[j];
        float cb = bo[0];
        for (int j = 0; j < 30; j++) cb += bf1[j] * v2[j];
        for (int j = 0; j < 20; j++) cb += bf2[j] * v3[j];
        for (int j = 0; j < 10; j++) cb += bf3[j] * Wo[j];
        g_cst[0] = c1; g_cst[1] = c2; g_cst[2] = cb;
    }
}

// --- t0[i] = x[i,:] . w1c  (warp per node, float2 per lane) -----------------
__global__ void k_t0(const float* __restrict__ x, int n) {
    int gw   = (blockIdx.x * blockDim.x + threadIdx.x) >> 5;
    int lane = threadIdx.x & 31;
    if (gw >= n) return;
    float2 xv = ((const float2*)x)[gw * 32 + lane];
    float acc = xv.x * g_w1c[2*lane] + xv.y * g_w1c[2*lane + 1];
    #pragma unroll
    for (int o = 16; o; o >>= 1) acc += __shfl_xor_sync(0xffffffffu, acc, o);
    if (lane == 0) { g_t[gw] = acc; g_p[gw] = g_dinv[gw] * acc; }
}

// --- per-edge gather + scatter: acc[dst] += p[src] --------------------------
__global__ void k_scatter(const void* ei, int E, int layer) {
    int e = blockIdx.x * blockDim.x + threadIdx.x;
    if (e >= E) return;
    int s = load_idx(ei, e);
    int d = load_idx(ei, E + e);
    float* acc = layer ? g_acc2 : g_acc1;
    atomicAdd(&acc[d], g_p[s]);
}

// --- finalize layer: t = dinv*(acc + dinv*t) + c ----------------------------
__global__ void k_fin(int layer, int n) {
    int i = blockIdx.x * blockDim.x + threadIdx.x;
    if (i >= n) return;
    const float* acc = layer ? g_acc2 : g_acc1;
    float di = g_dinv[i];
    float t  = di * (acc[i] + di * g_t[i]) + g_cst[layer];
    g_t[i] = t;
    if (layer == 0) g_p[i] = di * t;
}

__global__ void k_initout(float* out, int G) {
    int i = blockIdx.x * blockDim.x + threadIdx.x;
    if (i < G) out[i] = g_cst[2];
}

// --- pooled sum per graph (batch is sorted -> warp pre-reduction) -----------
__global__ void k_pool(const void* batch, float* out, int n) {
    int i    = blockIdx.x * blockDim.x + threadIdx.x;
    int lane = threadIdx.x & 31;
    int ic   = i < n ? i : (n - 1);
    int gid  = load_idx(batch, ic);
    float v  = (i < n) ? g_t[i] : 0.f;
    int g0   = __shfl_sync(0xffffffffu, gid, 0);
    bool uni = __all_sync(0xffffffffu, gid == g0);
    if (uni) {
        #pragma unroll
        for (int o = 16; o; o >>= 1) v += __shfl_xor_sync(0xffffffffu, v, o);
        if (lane == 0) atomicAdd(&out[g0], v);
    } else {
        atomicAdd(&out[gid], v);
    }
}

extern "C" void kernel_launch(void* const* d_in, const int* in_sizes, int n_in,
                              void* d_out, int out_size) {
    const float* x     = (const float*)d_in[0];
    const void*  ei    = d_in[1];
    const void*  batch = d_in[2];
    const float* W1  = (const float*)d_in[3],  *b1  = (const float*)d_in[4];
    const float* W2  = (const float*)d_in[5],  *b2  = (const float*)d_in[6];
    const float* Wf1 = (const float*)d_in[7],  *bf1 = (const float*)d_in[8];
    const float* Wf2 = (const float*)d_in[9],  *bf2 = (const float*)d_in[10];
    const float* Wf3 = (const float*)d_in[11], *bf3 = (const float*)d_in[12];
    const float* Wo  = (const float*)d_in[13], *bo  = (const float*)d_in[14];
    float* out = (float*)d_out;

    int E = in_sizes[1] / 2;     // 3.2M edges (element count same for i32/i64)
    int n = in_sizes[2];         // 100K nodes
    int G = out_size;            // 256 graphs

    int nb  = (n + 255) / 256;
    int ebn = (E + 255) / 256;

    k_detect<<<1, 32>>>((const int*)ei);
    k_zero<<<nb, 256>>>(n);
    k_deg<<<ebn, 256>>>(ei, E);
    k_dinv<<<nb, 256>>>(n);
    k_fold<<<1, 64>>>(W1, b1, W2, b2, Wf1, bf1, Wf2, bf2, Wf3, bf3, Wo, bo);
    k_t0<<<(n + 7) / 8, 256>>>(x, n);
    k_scatter<<<ebn, 256>>>(ei, E, 0);
    k_fin<<<nb, 256>>>(0, n);
    k_scatter<<<ebn, 256>>>(ei, E, 1);
    k_fin<<<nb, 256>>>(1, n);
    k_initout<<<1, 256>>>(out, G);
    k_pool<<<nb, 256>>>(batch, out, n);
}